// round 14
// baseline (speedup 1.0000x reference)
#include <cuda_runtime.h>
#include <cuda_bf16.h>
#include <cstdint>

// ---------------------------------------------------------------------------
// LIF layer: cur = X @ W^T + b via bf16x3-split GEMM on mma.sync (HMMA).
// R14: all 6 split-products merged into ONE GEMM kernel (BM=64, BN=64,
//      256 threads, 48KB single-buffered smem, 2 CTAs/SM). Main a0*b0 uses
//      the proven chain-4 + lo/hi drain; the 5 small products chain in a TC
//      accumulator across all ktiles (identical arithmetic to the previous
//      K1+K2 pair -> bit-identical output). Removes K1's low-density kernel
//      (55% tensor) and the g_cur RMW round-trip.
// ---------------------------------------------------------------------------

constexpr int T_DIM  = 64;
constexpr int B_DIM  = 128;
constexpr int IN_DIM = 2048;
constexpr int OUT_DIM = 2048;
constexpr int M_DIM  = T_DIM * B_DIM;          // 8192
constexpr float THR_V   = 1.0f;
constexpr float DECAY_V = 0.60653065971263342f; // exp(-1/2) rounded to fp32

// ------------------------------ scratch -----------------------------------
__device__ float g_cur[(size_t)M_DIM * OUT_DIM];                 // 64 MB
__device__ __nv_bfloat16 g_A0[(size_t)M_DIM * IN_DIM];           // 32 MB each
__device__ __nv_bfloat16 g_A1[(size_t)M_DIM * IN_DIM];
__device__ __nv_bfloat16 g_A2[(size_t)M_DIM * IN_DIM];
__device__ __nv_bfloat16 g_B0[(size_t)OUT_DIM * IN_DIM];         // 8 MB each
__device__ __nv_bfloat16 g_B1[(size_t)OUT_DIM * IN_DIM];
__device__ __nv_bfloat16 g_B2[(size_t)OUT_DIM * IN_DIM];

// ------------------------------ helpers -----------------------------------
__device__ __forceinline__ uint32_t smem_u32(const void* p) {
    uint32_t a;
    asm("{ .reg .u64 t; cvta.to.shared.u64 t, %1; cvt.u32.u64 %0, t; }"
        : "=r"(a) : "l"(p));
    return a;
}

#define SW128(o) ((o) ^ (((o) >> 3) & 0x70))

__device__ __forceinline__ void ldmx4(uint32_t* r, uint32_t addr) {
    asm volatile("ldmatrix.sync.aligned.m8n8.x4.shared.b16 {%0,%1,%2,%3}, [%4];"
                 : "=r"(r[0]), "=r"(r[1]), "=r"(r[2]), "=r"(r[3]) : "r"(addr));
}
// chained accumulate: d += a*b
__device__ __forceinline__ void mma16816(float* d, const uint32_t* a,
                                         const uint32_t* b) {
    asm volatile(
        "mma.sync.aligned.m16n8k16.row.col.f32.bf16.bf16.f32 "
        "{%0,%1,%2,%3}, {%4,%5,%6,%7}, {%8,%9}, {%0,%1,%2,%3};"
        : "+f"(d[0]), "+f"(d[1]), "+f"(d[2]), "+f"(d[3])
        : "r"(a[0]), "r"(a[1]), "r"(a[2]), "r"(a[3]), "r"(b[0]), "r"(b[1]));
}
// zero-C form: d = a*b
__device__ __forceinline__ void mma16816_z(float* d, const uint32_t* a,
                                           const uint32_t* b) {
    asm volatile(
        "mma.sync.aligned.m16n8k16.row.col.f32.bf16.bf16.f32 "
        "{%0,%1,%2,%3}, {%4,%5,%6,%7}, {%8,%9}, {%10,%11,%12,%13};"
        : "=f"(d[0]), "=f"(d[1]), "=f"(d[2]), "=f"(d[3])
        : "r"(a[0]), "r"(a[1]), "r"(a[2]), "r"(a[3]), "r"(b[0]), "r"(b[1]),
          "f"(0.0f), "f"(0.0f), "f"(0.0f), "f"(0.0f));
}

// ------------------------- split fp32 -> 3x bf16 ---------------------------
__device__ __forceinline__ void split3(float v, __nv_bfloat16& h0,
                                       __nv_bfloat16& h1, __nv_bfloat16& h2) {
    h0 = __float2bfloat16(v);
    float r1 = v - __bfloat162float(h0);
    h1 = __float2bfloat16(r1);
    float r2 = r1 - __bfloat162float(h1);
    h2 = __float2bfloat16(r2);
}

__global__ __launch_bounds__(256) void split_x_kernel(const float* __restrict__ src)
{
    int i = blockIdx.x * blockDim.x + threadIdx.x;
    float4 a = reinterpret_cast<const float4*>(src)[i];
    float v[4] = {a.x, a.y, a.z, a.w};
    __nv_bfloat16 h0[4], h1[4], h2[4];
#pragma unroll
    for (int j = 0; j < 4; j++) split3(v[j], h0[j], h1[j], h2[j]);
    __nv_bfloat162 p;
    p = {h0[0], h0[1]}; reinterpret_cast<__nv_bfloat162*>(g_A0)[2*i  ] = p;
    p = {h0[2], h0[3]}; reinterpret_cast<__nv_bfloat162*>(g_A0)[2*i+1] = p;
    p = {h1[0], h1[1]}; reinterpret_cast<__nv_bfloat162*>(g_A1)[2*i  ] = p;
    p = {h1[2], h1[3]}; reinterpret_cast<__nv_bfloat162*>(g_A1)[2*i+1] = p;
    p = {h2[0], h2[1]}; reinterpret_cast<__nv_bfloat162*>(g_A2)[2*i  ] = p;
    p = {h2[2], h2[3]}; reinterpret_cast<__nv_bfloat162*>(g_A2)[2*i+1] = p;
}

__global__ __launch_bounds__(256) void split_w_kernel(const float* __restrict__ src)
{
    int i = blockIdx.x * blockDim.x + threadIdx.x;
    float4 a = reinterpret_cast<const float4*>(src)[i];
    float v[4] = {a.x, a.y, a.z, a.w};
    __nv_bfloat16 h0[4], h1[4], h2[4];
#pragma unroll
    for (int j = 0; j < 4; j++) split3(v[j], h0[j], h1[j], h2[j]);
    __nv_bfloat162 p;
    p = {h0[0], h0[1]}; reinterpret_cast<__nv_bfloat162*>(g_B0)[2*i  ] = p;
    p = {h0[2], h0[3]}; reinterpret_cast<__nv_bfloat162*>(g_B0)[2*i+1] = p;
    p = {h1[0], h1[1]}; reinterpret_cast<__nv_bfloat162*>(g_B1)[2*i  ] = p;
    p = {h1[2], h1[3]}; reinterpret_cast<__nv_bfloat162*>(g_B1)[2*i+1] = p;
    p = {h2[0], h2[1]}; reinterpret_cast<__nv_bfloat162*>(g_B2)[2*i  ] = p;
    p = {h2[2], h2[3]}; reinterpret_cast<__nv_bfloat162*>(g_B2)[2*i+1] = p;
}

// ------------------------------ GEMM kernel --------------------------------
// BM=64, BN=64, BK=64. 256 threads = 8 warps (4 wm x 2 wn), warp tile 16x32.
// 6 tiles x 8KB = 48 KB single-buffered smem -> 2 CTAs/SM (regs ~100).
constexpr int BM = 64, BN = 64, BK = 64;
constexpr int NST = IN_DIM / BK;              // 32 ktiles
constexpr int TILE = 64 * 128;                // 8 KB per tile (64 rows x 128B)
constexpr int G_SMEM = 6 * TILE;              // 49152

__global__ __launch_bounds__(256, 2)
void gemm6_kernel(const float* __restrict__ bias)
{
    extern __shared__ char smem[];
    const uint32_t sb = smem_u32(smem);
    const int tid  = threadIdx.x;
    const int wid  = tid >> 5;
    const int lane = tid & 31;
    const int bm = blockIdx.y * BM;
    const int bn = blockIdx.x * BN;
    const int warp_m = wid & 3;      // 0..3 (16 rows each)
    const int warp_n = wid >> 2;     // 0..1 (32 cols each)
    const int mi = lane >> 3, r8 = lane & 7;

    const __nv_bfloat16* srcA[3] = {
        g_A0 + (size_t)bm * IN_DIM, g_A1 + (size_t)bm * IN_DIM,
        g_A2 + (size_t)bm * IN_DIM };
    const __nv_bfloat16* srcB[3] = {
        g_B0 + (size_t)bn * IN_DIM, g_B1 + (size_t)bn * IN_DIM,
        g_B2 + (size_t)bn * IN_DIM };

    auto stage_load = [&](int s) {
        const int k0 = s * BK;
#pragma unroll
        for (int t = 0; t < 6; t++) {
            const __nv_bfloat16* base = (t < 3) ? srcA[t] : srcB[t - 3];
            uint32_t stile = sb + t * TILE;
#pragma unroll
            for (int u = 0; u < 2; u++) {
                int v = tid + 256 * u;          // 0..511
                int row = v >> 3;               // 0..63
                int c = (v & 7) * 16;
                const void* g = (const char*)(base + (size_t)row * IN_DIM + k0) + c;
                asm volatile("cp.async.cg.shared.global [%0], [%1], 16;"
                             :: "r"(stile + SW128(row * 128 + c)), "l"(g));
            }
        }
        asm volatile("cp.async.commit_group;" ::: "memory");
    };

    // accumulators: main hi/lo (fp32 drain) + tmp (chain-4) + accs (smalls)
    float hi[4][4], lo[4][4], accs[4][4];
#pragma unroll
    for (int nf = 0; nf < 4; nf++)
#pragma unroll
        for (int j = 0; j < 4; j++) {
            hi[nf][j] = 0.0f; lo[nf][j] = 0.0f; accs[nf][j] = 0.0f;
        }

    stage_load(0);

    for (int s = 0; s < NST; s++) {
        asm volatile("cp.async.wait_group 0;" ::: "memory");
        __syncthreads();

        float tmp[4][4];                        // chain-4 over this ktile
#pragma unroll
        for (int ks = 0; ks < 4; ks++) {
            const int kb_a = ks * 32 + (mi >> 1) * 16;
            const int kb_b = ks * 32 + (mi & 1) * 16;
            const int arow = warp_m * 16 + (mi & 1) * 8 + r8;

            uint32_t af[3][4];                  // A frags, one per split
#pragma unroll
            for (int t = 0; t < 3; t++)
                ldmx4(af[t], sb + t * TILE + SW128(arow * 128 + kb_a));

            uint32_t bfr[2][4];                 // B frags, per b-split
            // b0: main (a0, chain-4 into tmp) + smalls a1,a2
#pragma unroll
            for (int np = 0; np < 2; np++) {
                int n = warp_n * 32 + np * 16 + (mi >> 1) * 8 + r8;
                ldmx4(bfr[np], sb + 3 * TILE + SW128(n * 128 + kb_b));
            }
            if (ks == 0) {
#pragma unroll
                for (int nf = 0; nf < 4; nf++)
                    mma16816_z(tmp[nf], af[0], &bfr[nf >> 1][(nf & 1) * 2]);
            } else {
#pragma unroll
                for (int nf = 0; nf < 4; nf++)
                    mma16816(tmp[nf], af[0], &bfr[nf >> 1][(nf & 1) * 2]);
            }
#pragma unroll
            for (int nf = 0; nf < 4; nf++)
                mma16816(accs[nf], af[1], &bfr[nf >> 1][(nf & 1) * 2]);
#pragma unroll
            for (int nf = 0; nf < 4; nf++)
                mma16816(accs[nf], af[2], &bfr[nf >> 1][(nf & 1) * 2]);

            // b1: smalls a0, a1
#pragma unroll
            for (int np = 0; np < 2; np++) {
                int n = warp_n * 32 + np * 16 + (mi >> 1) * 8 + r8;
                ldmx4(bfr[np], sb + 4 * TILE + SW128(n * 128 + kb_b));
            }
#pragma unroll
            for (int nf = 0; nf < 4; nf++)
                mma16816(accs[nf], af[0], &bfr[nf >> 1][(nf & 1) * 2]);
#pragma unroll
            for (int nf = 0; nf < 4; nf++)
                mma16816(accs[nf], af[1], &bfr[nf >> 1][(nf & 1) * 2]);

            // b2: small a0
#pragma unroll
            for (int np = 0; np < 2; np++) {
                int n = warp_n * 32 + np * 16 + (mi >> 1) * 8 + r8;
                ldmx4(bfr[np], sb + 5 * TILE + SW128(n * 128 + kb_b));
            }
#pragma unroll
            for (int nf = 0; nf < 4; nf++)
                mma16816(accs[nf], af[0], &bfr[nf >> 1][(nf & 1) * 2]);
        }

        // drain chain-4 into lo (16 FADD per ktile)
#pragma unroll
        for (int nf = 0; nf < 4; nf++)
#pragma unroll
            for (int j = 0; j < 4; j++)
                lo[nf][j] = __fadd_rn(lo[nf][j], tmp[nf][j]);

        if ((s & 3) == 3) {                     // flush lo -> hi every 4 ktiles
#pragma unroll
            for (int nf = 0; nf < 4; nf++)
#pragma unroll
                for (int j = 0; j < 4; j++) {
                    hi[nf][j] = __fadd_rn(hi[nf][j], lo[nf][j]);
                    lo[nf][j] = 0.0f;
                }
        }
        __syncthreads();                        // WAR before reload
        if (s + 1 < NST) stage_load(s + 1);
    }

    // Epilogue: (hi + bias) + accs -> g_cur  (same FADD order as K1->K2 pair)
    const int qr = lane >> 2;
    const int qc = (lane & 3) * 2;
#pragma unroll
    for (int h = 0; h < 2; h++) {
        int row = bm + warp_m * 16 + h * 8 + qr;
        float* dst = g_cur + (size_t)row * OUT_DIM + bn + warp_n * 32 + qc;
        const float* bp = bias + bn + warp_n * 32 + qc;
#pragma unroll
        for (int nf = 0; nf < 4; nf++) {
            float2 v;
            v.x = __fadd_rn(__fadd_rn(hi[nf][h*2+0], bp[nf*8+0]), accs[nf][h*2+0]);
            v.y = __fadd_rn(__fadd_rn(hi[nf][h*2+1], bp[nf*8+1]), accs[nf][h*2+1]);
            *reinterpret_cast<float2*>(dst + nf * 8) = v;
        }
    }
}

// ------------------------------ LIF scan -----------------------------------
__global__ __launch_bounds__(256) void lif_scan_kernel(float* __restrict__ out)
{
    const int idx = blockIdx.x * blockDim.x + threadIdx.x;
    const int BO  = B_DIM * OUT_DIM;
    float mem = 0.0f;
#pragma unroll
    for (int t = 0; t < T_DIM; t++) {
        float c = g_cur[(size_t)t * BO + idx];
        mem = __fadd_rn(__fmul_rn(mem, DECAY_V), c);
        float spk = (__fadd_rn(mem, -THR_V) > 0.0f) ? 1.0f : 0.0f;
        mem = __fadd_rn(mem, -spk * THR_V);
        out[(size_t)t * BO + idx] = spk;
    }
}

// ---------------------------------------------------------------------------
extern "C" void kernel_launch(void* const* d_in, const int* in_sizes, int n_in,
                              void* d_out, int out_size)
{
    const float* x = (const float*)d_in[0];
    const float* W = (const float*)d_in[1];
    const float* b = (const float*)d_in[2];
    float* out = (float*)d_out;

    split_x_kernel<<<(M_DIM * (size_t)IN_DIM / 4) / 256, 256>>>(x);
    split_w_kernel<<<(OUT_DIM * (size_t)IN_DIM / 4) / 256, 256>>>(W);

    cudaFuncSetAttribute(gemm6_kernel,
                         cudaFuncAttributeMaxDynamicSharedMemorySize, G_SMEM);
    dim3 grid(OUT_DIM / BN, M_DIM / BM);      // (32, 128)
    gemm6_kernel<<<grid, 256, G_SMEM>>>(b);

    lif_scan_kernel<<<(B_DIM * OUT_DIM) / 256, 256>>>(out);
}

// round 16
// speedup vs baseline: 1.0097x; 1.0097x over previous
#include <cuda_runtime.h>
#include <cuda_bf16.h>
#include <cstdint>

// ---------------------------------------------------------------------------
// LIF layer: cur = X @ W^T + b via bf16x3-split GEMM on mma.sync (HMMA).
// R16: R13 base (K2 = proven 686us kernel). K1 = R13's K1 with BK widened
//      64->128 via k-chunked tiles ([kc][row][128B], SW128 applied within each
//      128B row -- fixing R15's swizzle-decomposition bug). 2x mma density per
//      stage, half the barriers, same arithmetic order (bit-identical output).
// ---------------------------------------------------------------------------

constexpr int T_DIM  = 64;
constexpr int B_DIM  = 128;
constexpr int IN_DIM = 2048;
constexpr int OUT_DIM = 2048;
constexpr int M_DIM  = T_DIM * B_DIM;          // 8192
constexpr float THR_V   = 1.0f;
constexpr float DECAY_V = 0.60653065971263342f; // exp(-1/2) rounded to fp32

// ------------------------------ scratch -----------------------------------
__device__ float g_cur[(size_t)M_DIM * OUT_DIM];                 // 64 MB
__device__ __nv_bfloat16 g_A0[(size_t)M_DIM * IN_DIM];           // 32 MB each
__device__ __nv_bfloat16 g_A1[(size_t)M_DIM * IN_DIM];
__device__ __nv_bfloat16 g_A2[(size_t)M_DIM * IN_DIM];
__device__ __nv_bfloat16 g_B0[(size_t)OUT_DIM * IN_DIM];         // 8 MB each
__device__ __nv_bfloat16 g_B1[(size_t)OUT_DIM * IN_DIM];
__device__ __nv_bfloat16 g_B2[(size_t)OUT_DIM * IN_DIM];

// ------------------------------ helpers -----------------------------------
__device__ __forceinline__ uint32_t smem_u32(const void* p) {
    uint32_t a;
    asm("{ .reg .u64 t; cvta.to.shared.u64 t, %1; cvt.u32.u64 %0, t; }"
        : "=r"(a) : "l"(p));
    return a;
}

#define SW128(o) ((o) ^ (((o) >> 3) & 0x70))

__device__ __forceinline__ void ldmx4(uint32_t* r, uint32_t addr) {
    asm volatile("ldmatrix.sync.aligned.m8n8.x4.shared.b16 {%0,%1,%2,%3}, [%4];"
                 : "=r"(r[0]), "=r"(r[1]), "=r"(r[2]), "=r"(r[3]) : "r"(addr));
}
// chained accumulate: d += a*b
__device__ __forceinline__ void mma16816(float* d, const uint32_t* a,
                                         const uint32_t* b) {
    asm volatile(
        "mma.sync.aligned.m16n8k16.row.col.f32.bf16.bf16.f32 "
        "{%0,%1,%2,%3}, {%4,%5,%6,%7}, {%8,%9}, {%0,%1,%2,%3};"
        : "+f"(d[0]), "+f"(d[1]), "+f"(d[2]), "+f"(d[3])
        : "r"(a[0]), "r"(a[1]), "r"(a[2]), "r"(a[3]), "r"(b[0]), "r"(b[1]));
}
// zero-C form: d = a*b
__device__ __forceinline__ void mma16816_z(float* d, const uint32_t* a,
                                           const uint32_t* b) {
    asm volatile(
        "mma.sync.aligned.m16n8k16.row.col.f32.bf16.bf16.f32 "
        "{%0,%1,%2,%3}, {%4,%5,%6,%7}, {%8,%9}, {%10,%11,%12,%13};"
        : "=f"(d[0]), "=f"(d[1]), "=f"(d[2]), "=f"(d[3])
        : "r"(a[0]), "r"(a[1]), "r"(a[2]), "r"(a[3]), "r"(b[0]), "r"(b[1]),
          "f"(0.0f), "f"(0.0f), "f"(0.0f), "f"(0.0f));
}

// ------------------------- split fp32 -> 3x bf16 ---------------------------
__device__ __forceinline__ void split3(float v, __nv_bfloat16& h0,
                                       __nv_bfloat16& h1, __nv_bfloat16& h2) {
    h0 = __float2bfloat16(v);
    float r1 = v - __bfloat162float(h0);
    h1 = __float2bfloat16(r1);
    float r2 = r1 - __bfloat162float(h1);
    h2 = __float2bfloat16(r2);
}

__global__ __launch_bounds__(256) void split_x_kernel(const float* __restrict__ src)
{
    int i = blockIdx.x * blockDim.x + threadIdx.x;
    float4 a = reinterpret_cast<const float4*>(src)[i];
    float v[4] = {a.x, a.y, a.z, a.w};
    __nv_bfloat16 h0[4], h1[4], h2[4];
#pragma unroll
    for (int j = 0; j < 4; j++) split3(v[j], h0[j], h1[j], h2[j]);
    __nv_bfloat162 p;
    p = {h0[0], h0[1]}; reinterpret_cast<__nv_bfloat162*>(g_A0)[2*i  ] = p;
    p = {h0[2], h0[3]}; reinterpret_cast<__nv_bfloat162*>(g_A0)[2*i+1] = p;
    p = {h1[0], h1[1]}; reinterpret_cast<__nv_bfloat162*>(g_A1)[2*i  ] = p;
    p = {h1[2], h1[3]}; reinterpret_cast<__nv_bfloat162*>(g_A1)[2*i+1] = p;
    p = {h2[0], h2[1]}; reinterpret_cast<__nv_bfloat162*>(g_A2)[2*i  ] = p;
    p = {h2[2], h2[3]}; reinterpret_cast<__nv_bfloat162*>(g_A2)[2*i+1] = p;
}

__global__ __launch_bounds__(256) void split_w_kernel(const float* __restrict__ src)
{
    int i = blockIdx.x * blockDim.x + threadIdx.x;
    float4 a = reinterpret_cast<const float4*>(src)[i];
    float v[4] = {a.x, a.y, a.z, a.w};
    __nv_bfloat16 h0[4], h1[4], h2[4];
#pragma unroll
    for (int j = 0; j < 4; j++) split3(v[j], h0[j], h1[j], h2[j]);
    __nv_bfloat162 p;
    p = {h0[0], h0[1]}; reinterpret_cast<__nv_bfloat162*>(g_B0)[2*i  ] = p;
    p = {h0[2], h0[3]}; reinterpret_cast<__nv_bfloat162*>(g_B0)[2*i+1] = p;
    p = {h1[0], h1[1]}; reinterpret_cast<__nv_bfloat162*>(g_B1)[2*i  ] = p;
    p = {h1[2], h1[3]}; reinterpret_cast<__nv_bfloat162*>(g_B1)[2*i+1] = p;
    p = {h2[0], h2[1]}; reinterpret_cast<__nv_bfloat162*>(g_B2)[2*i  ] = p;
    p = {h2[2], h2[3]}; reinterpret_cast<__nv_bfloat162*>(g_B2)[2*i+1] = p;
}

// ============================ K1: main a0*b0 ================================
// BM=128, BN=64, BK=128. 256 threads = 8 warps (4 wm x 2 wn), warp tile 32x32.
// Tiles k-chunked: A = [2 kc][128 rows][128B] = 32KB, B = [2 kc][64 rows][128B]
// = 16KB. Double-buffered (96KB) -> 2 CTAs/SM. 16 stages, 64 mma/warp/stage.
// Drain: chain-4 groups, lo += group; lo -> hi every 2 stages (= 256 k elems,
// identical cadence and order to R13 -> bit-identical output).
constexpr int K1_BK   = 128;
constexpr int K1_NST  = IN_DIM / K1_BK;       // 16 stages
constexpr int K1_ACH  = 128 * 128;            // 16 KB per A kchunk
constexpr int K1_BCH  = 64 * 128;             // 8 KB per B kchunk
constexpr int K1_ATILE = 2 * K1_ACH;          // 32 KB
constexpr int K1_BTILE = 2 * K1_BCH;          // 16 KB
constexpr int K1_BUF  = K1_ATILE + K1_BTILE;  // 48 KB per buffer
constexpr int K1_SMEM = 2 * K1_BUF;           // 98304

__global__ __launch_bounds__(256, 2)
void gemm_main_kernel(const float* __restrict__ bias)
{
    extern __shared__ char smem[];
    const uint32_t sb = smem_u32(smem);
    const int tid  = threadIdx.x;
    const int wid  = tid >> 5;
    const int lane = tid & 31;
    const int bm = blockIdx.y * 128;
    const int bn = blockIdx.x * 64;
    const int warp_m = wid & 3;
    const int warp_n = wid >> 2;
    const int mi = lane >> 3, r8 = lane & 7;

    const __nv_bfloat16* Asrc = g_A0 + (size_t)bm * IN_DIM;
    const __nv_bfloat16* Bsrc = g_B0 + (size_t)bn * IN_DIM;

    auto stage_load = [&](int s) {
        const int buf = s & 1;
        const int k0 = s * K1_BK;
        const uint32_t sA = sb + buf * K1_BUF;
        const uint32_t sB = sA + K1_ATILE;
        // A: 2048 16B chunks (8 per thread)
#pragma unroll
        for (int u = 0; u < 8; u++) {
            int v = tid + 256 * u;              // 0..2047
            int kc = v >> 10;                   // kchunk 0..1
            int r  = (v >> 3) & 127;            // row 0..127
            int cb = (v & 7) * 16;              // byte col in 128B row
            const char* g = (const char*)(Asrc + (size_t)r * IN_DIM + k0 + kc * 64) + cb;
            asm volatile("cp.async.cg.shared.global [%0], [%1], 16;"
                         :: "r"(sA + kc * K1_ACH + SW128(r * 128 + cb)), "l"(g));
        }
        // B: 1024 16B chunks (4 per thread)
#pragma unroll
        for (int u = 0; u < 4; u++) {
            int v = tid + 256 * u;              // 0..1023
            int kc = v >> 9;                    // kchunk 0..1
            int r  = (v >> 3) & 63;             // row 0..63
            int cb = (v & 7) * 16;
            const char* g = (const char*)(Bsrc + (size_t)r * IN_DIM + k0 + kc * 64) + cb;
            asm volatile("cp.async.cg.shared.global [%0], [%1], 16;"
                         :: "r"(sB + kc * K1_BCH + SW128(r * 128 + cb)), "l"(g));
        }
        asm volatile("cp.async.commit_group;" ::: "memory");
    };

    float hi[2][4][4], lo[2][4][4];
#pragma unroll
    for (int mt = 0; mt < 2; mt++)
#pragma unroll
        for (int nf = 0; nf < 4; nf++)
#pragma unroll
            for (int j = 0; j < 4; j++) { hi[mt][nf][j] = 0.0f; lo[mt][nf][j] = 0.0f; }

    stage_load(0);

    for (int s = 0; s < K1_NST; s++) {
        if (s + 1 < K1_NST) {
            stage_load(s + 1);
            asm volatile("cp.async.wait_group 1;" ::: "memory");
        } else {
            asm volatile("cp.async.wait_group 0;" ::: "memory");
        }
        __syncthreads();

        const uint32_t sA = sb + (s & 1) * K1_BUF;
        const uint32_t sB = sA + K1_ATILE;

        // 8 k16 steps = 2 chain-4 groups
#pragma unroll
        for (int grp = 0; grp < 2; grp++) {
            float tmp[2][4][4];
#pragma unroll
            for (int q = 0; q < 4; q++) {
                const int ks = grp * 4 + q;
                const uint32_t aoff = (ks >> 2) * K1_ACH;
                const uint32_t boff = (ks >> 2) * K1_BCH;
                const int ik = (ks & 3) * 32;
                const int kb_a = ik + (mi >> 1) * 16;
                const int kb_b = ik + (mi & 1) * 16;
                uint32_t af[2][4];
                uint32_t bfr[2][4];
#pragma unroll
                for (int mt = 0; mt < 2; mt++) {
                    int row = warp_m * 32 + mt * 16 + (mi & 1) * 8 + r8;
                    ldmx4(af[mt], sA + aoff + SW128(row * 128 + kb_a));
                }
#pragma unroll
                for (int np = 0; np < 2; np++) {
                    int n = warp_n * 32 + np * 16 + (mi >> 1) * 8 + r8;
                    ldmx4(bfr[np], sB + boff + SW128(n * 128 + kb_b));
                }
                if (q == 0) {
#pragma unroll
                    for (int mt = 0; mt < 2; mt++)
#pragma unroll
                        for (int nf = 0; nf < 4; nf++)
                            mma16816_z(tmp[mt][nf], af[mt], &bfr[nf >> 1][(nf & 1) * 2]);
                } else {
#pragma unroll
                    for (int mt = 0; mt < 2; mt++)
#pragma unroll
                        for (int nf = 0; nf < 4; nf++)
                            mma16816(tmp[mt][nf], af[mt], &bfr[nf >> 1][(nf & 1) * 2]);
                }
            }
#pragma unroll
            for (int mt = 0; mt < 2; mt++)
#pragma unroll
                for (int nf = 0; nf < 4; nf++)
#pragma unroll
                    for (int j = 0; j < 4; j++)
                        lo[mt][nf][j] = __fadd_rn(lo[mt][nf][j], tmp[mt][nf][j]);
        }

        if ((s & 1) == 1) {     // flush lo -> hi every 2 stages (256 k elems)
#pragma unroll
            for (int mt = 0; mt < 2; mt++)
#pragma unroll
                for (int nf = 0; nf < 4; nf++)
#pragma unroll
                    for (int j = 0; j < 4; j++) {
                        hi[mt][nf][j] = __fadd_rn(hi[mt][nf][j], lo[mt][nf][j]);
                        lo[mt][nf][j] = 0.0f;
                    }
        }
        __syncthreads();
    }

    // Epilogue: hi + bias -> g_cur
    const int qr = lane >> 2;
    const int qc = (lane & 3) * 2;
#pragma unroll
    for (int mt = 0; mt < 2; mt++)
#pragma unroll
        for (int h = 0; h < 2; h++) {
            int row = bm + warp_m * 32 + mt * 16 + h * 8 + qr;
            float* dst = g_cur + (size_t)row * OUT_DIM + bn + warp_n * 32 + qc;
            const float* bp = bias + bn + warp_n * 32 + qc;
#pragma unroll
            for (int nf = 0; nf < 4; nf++) {
                float2 v;
                v.x = __fadd_rn(hi[mt][nf][h*2+0], bp[nf*8+0]);
                v.y = __fadd_rn(hi[mt][nf][h*2+1], bp[nf*8+1]);
                *reinterpret_cast<float2*>(dst + nf * 8) = v;
            }
        }
}

// ====================== K2: 5 small split-combos ============================
// R11/R13 proven kernel: BM=128, BN=64, BK=64, 256 threads, warp tile 32x32,
// 72KB single-buffered smem, 3 CTAs/SM.
constexpr int BM2 = 128, BN2 = 64, BK2 = 64;
constexpr int NST2 = IN_DIM / BK2;            // 32
constexpr int TILE_A  = 128 * 128;            // 16 KB
constexpr int TILE_BB = 64 * 128;             // 8 KB
constexpr int K2_SMEM = 3 * TILE_A + 3 * TILE_BB;  // 73728

__global__ __launch_bounds__(256, 3)
void gemm_small_kernel()
{
    extern __shared__ char smem[];
    const uint32_t sb = smem_u32(smem);
    const int tid  = threadIdx.x;
    const int wid  = tid >> 5;
    const int lane = tid & 31;
    const int bm = blockIdx.y * BM2;
    const int bn = blockIdx.x * BN2;
    const int warp_m = wid & 3;
    const int warp_n = wid >> 2;

    const __nv_bfloat16* srcA[3] = {
        g_A0 + (size_t)bm * IN_DIM, g_A1 + (size_t)bm * IN_DIM,
        g_A2 + (size_t)bm * IN_DIM };
    const __nv_bfloat16* srcB[3] = {
        g_B0 + (size_t)bn * IN_DIM, g_B1 + (size_t)bn * IN_DIM,
        g_B2 + (size_t)bn * IN_DIM };

    auto stage_load = [&](int s) {
        const int k0 = s * BK2;
#pragma unroll
        for (int t = 0; t < 3; t++) {
            const __nv_bfloat16* base = srcA[t] + k0;
            uint32_t stile = sb + t * TILE_A;
#pragma unroll
            for (int u = 0; u < 4; u++) {
                int v = tid + 256 * u;
                int row = v >> 3;
                int c = (v & 7) * 16;
                const void* g = (const char*)(base + (size_t)row * IN_DIM) + c;
                asm volatile("cp.async.cg.shared.global [%0], [%1], 16;"
                             :: "r"(stile + SW128(row * 128 + c)), "l"(g));
            }
        }
#pragma unroll
        for (int t = 0; t < 3; t++) {
            const __nv_bfloat16* base = srcB[t] + k0;
            uint32_t stile = sb + 3 * TILE_A + t * TILE_BB;
#pragma unroll
            for (int u = 0; u < 2; u++) {
                int v = tid + 256 * u;
                int row = v >> 3;
                int c = (v & 7) * 16;
                const void* g = (const char*)(base + (size_t)row * IN_DIM) + c;
                asm volatile("cp.async.cg.shared.global [%0], [%1], 16;"
                             :: "r"(stile + SW128(row * 128 + c)), "l"(g));
            }
        }
        asm volatile("cp.async.commit_group;" ::: "memory");
    };

    float accs[2][4][4];
#pragma unroll
    for (int mt = 0; mt < 2; mt++)
#pragma unroll
        for (int nf = 0; nf < 4; nf++)
#pragma unroll
            for (int j = 0; j < 4; j++) accs[mt][nf][j] = 0.0f;

    const int mi = lane >> 3, r8 = lane & 7;

    stage_load(0);

    for (int s = 0; s < NST2; s++) {
        asm volatile("cp.async.wait_group 0;" ::: "memory");
        __syncthreads();

#pragma unroll
        for (int ks = 0; ks < 4; ks++) {
            const int kb_a = ks * 32 + (mi >> 1) * 16;
            const int kb_b = ks * 32 + (mi & 1) * 16;
            constexpr int NA[3]    = {2, 2, 1};
            constexpr int AI[3][2] = {{1, 2}, {0, 1}, {0, 0}};
#pragma unroll
            for (int bsp = 0; bsp < 3; bsp++) {
                uint32_t bfr[2][4];
#pragma unroll
                for (int np = 0; np < 2; np++) {
                    int n = warp_n * 32 + np * 16 + (mi >> 1) * 8 + r8;
                    ldmx4(bfr[np], sb + 3 * TILE_A + bsp * TILE_BB +
                                   SW128(n * 128 + kb_b));
                }
#pragma unroll
                for (int ai = 0; ai < 2; ai++) {
                    if (ai < NA[bsp]) {
                        uint32_t af[2][4];
#pragma unroll
                        for (int mt = 0; mt < 2; mt++) {
                            int row = warp_m * 32 + mt * 16 + (mi & 1) * 8 + r8;
                            ldmx4(af[mt], sb + AI[bsp][ai] * TILE_A +
                                          SW128(row * 128 + kb_a));
                        }
#pragma unroll
                        for (int mt = 0; mt < 2; mt++)
#pragma unroll
                            for (int nf = 0; nf < 4; nf++)
                                mma16816(accs[mt][nf], af[mt],
                                         &bfr[nf >> 1][(nf & 1) * 2]);
                    }
                }
            }
        }
        __syncthreads();
        if (s + 1 < NST2) stage_load(s + 1);
    }

    const int qr = lane >> 2;
    const int qc = (lane & 3) * 2;
#pragma unroll
    for (int mt = 0; mt < 2; mt++)
#pragma unroll
        for (int h = 0; h < 2; h++) {
            int row = bm + warp_m * 32 + mt * 16 + h * 8 + qr;
            float* dst = g_cur + (size_t)row * OUT_DIM + bn + warp_n * 32 + qc;
#pragma unroll
            for (int nf = 0; nf < 4; nf++) {
                float2 v = *reinterpret_cast<float2*>(dst + nf * 8);
                v.x = __fadd_rn(v.x, accs[mt][nf][h*2+0]);
                v.y = __fadd_rn(v.y, accs[mt][nf][h*2+1]);
                *reinterpret_cast<float2*>(dst + nf * 8) = v;
            }
        }
}

// ------------------------------ LIF scan -----------------------------------
__global__ __launch_bounds__(256) void lif_scan_kernel(float* __restrict__ out)
{
    const int idx = blockIdx.x * blockDim.x + threadIdx.x;
    const int BO  = B_DIM * OUT_DIM;
    float mem = 0.0f;
#pragma unroll
    for (int t = 0; t < T_DIM; t++) {
        float c = g_cur[(size_t)t * BO + idx];
        mem = __fadd_rn(__fmul_rn(mem, DECAY_V), c);
        float spk = (__fadd_rn(mem, -THR_V) > 0.0f) ? 1.0f : 0.0f;
        mem = __fadd_rn(mem, -spk * THR_V);
        out[(size_t)t * BO + idx] = spk;
    }
}

// ---------------------------------------------------------------------------
extern "C" void kernel_launch(void* const* d_in, const int* in_sizes, int n_in,
                              void* d_out, int out_size)
{
    const float* x = (const float*)d_in[0];
    const float* W = (const float*)d_in[1];
    const float* b = (const float*)d_in[2];
    float* out = (float*)d_out;

    split_x_kernel<<<(M_DIM * (size_t)IN_DIM / 4) / 256, 256>>>(x);
    split_w_kernel<<<(OUT_DIM * (size_t)IN_DIM / 4) / 256, 256>>>(W);

    cudaFuncSetAttribute(gemm_main_kernel,
                         cudaFuncAttributeMaxDynamicSharedMemorySize, K1_SMEM);
    dim3 grid1(OUT_DIM / 64, M_DIM / 128);    // (32, 64)
    gemm_main_kernel<<<grid1, 256, K1_SMEM>>>(b);

    cudaFuncSetAttribute(gemm_small_kernel,
                         cudaFuncAttributeMaxDynamicSharedMemorySize, K2_SMEM);
    dim3 grid2(OUT_DIM / BN2, M_DIM / BM2);   // (32, 64)
    gemm_small_kernel<<<grid2, 256, K2_SMEM>>>();

    lif_scan_kernel<<<(B_DIM * OUT_DIM) / 256, 256>>>(out);
}

// round 17
// speedup vs baseline: 1.4555x; 1.4415x over previous
#include <cuda_runtime.h>
#include <cuda_fp16.h>
#include <cstdint>

// ---------------------------------------------------------------------------
// LIF layer: cur = X @ W^T + b via fp16x2-split GEMM on mma.sync (HMMA).
// R17: bf16x3 (6 products) -> fp16x2 (3 products). W pre-scaled by 4096 so
//      its fp16 residuals stay normal; epilogue multiplies by 1/4096 (exact).
//      One merged GEMM kernel: main a0*b0 chain-4 -> RN drain into hi;
//      smalls (a0*b1, a1*b0) TC-chained per stage -> drained into hi.
//      Dropped-term error ~1.4e-7, total ~2.2e-7 (R9-level, passes).
// ---------------------------------------------------------------------------

constexpr int T_DIM  = 64;
constexpr int B_DIM  = 128;
constexpr int IN_DIM = 2048;
constexpr int OUT_DIM = 2048;
constexpr int M_DIM  = T_DIM * B_DIM;          // 8192
constexpr float THR_V   = 1.0f;
constexpr float DECAY_V = 0.60653065971263342f; // exp(-1/2) rounded to fp32
constexpr float WSCALE  = 4096.0f;
constexpr float INVWS   = 1.0f / 4096.0f;       // exact power of 2

// ------------------------------ scratch -----------------------------------
__device__ float g_cur[(size_t)M_DIM * OUT_DIM];                 // 64 MB
__device__ __half g_A0h[(size_t)M_DIM * IN_DIM];                 // 32 MB each
__device__ __half g_A1h[(size_t)M_DIM * IN_DIM];
__device__ __half g_B0h[(size_t)OUT_DIM * IN_DIM];               // 8 MB each
__device__ __half g_B1h[(size_t)OUT_DIM * IN_DIM];

// ------------------------------ helpers -----------------------------------
__device__ __forceinline__ uint32_t smem_u32(const void* p) {
    uint32_t a;
    asm("{ .reg .u64 t; cvta.to.shared.u64 t, %1; cvt.u32.u64 %0, t; }"
        : "=r"(a) : "l"(p));
    return a;
}

#define SW128(o) ((o) ^ (((o) >> 3) & 0x70))

__device__ __forceinline__ void ldmx4(uint32_t* r, uint32_t addr) {
    asm volatile("ldmatrix.sync.aligned.m8n8.x4.shared.b16 {%0,%1,%2,%3}, [%4];"
                 : "=r"(r[0]), "=r"(r[1]), "=r"(r[2]), "=r"(r[3]) : "r"(addr));
}
// chained accumulate: d += a*b  (fp16 inputs, fp32 acc)
__device__ __forceinline__ void mma16816(float* d, const uint32_t* a,
                                         const uint32_t* b) {
    asm volatile(
        "mma.sync.aligned.m16n8k16.row.col.f32.f16.f16.f32 "
        "{%0,%1,%2,%3}, {%4,%5,%6,%7}, {%8,%9}, {%0,%1,%2,%3};"
        : "+f"(d[0]), "+f"(d[1]), "+f"(d[2]), "+f"(d[3])
        : "r"(a[0]), "r"(a[1]), "r"(a[2]), "r"(a[3]), "r"(b[0]), "r"(b[1]));
}
// zero-C form: d = a*b
__device__ __forceinline__ void mma16816_z(float* d, const uint32_t* a,
                                           const uint32_t* b) {
    asm volatile(
        "mma.sync.aligned.m16n8k16.row.col.f32.f16.f16.f32 "
        "{%0,%1,%2,%3}, {%4,%5,%6,%7}, {%8,%9}, {%10,%11,%12,%13};"
        : "=f"(d[0]), "=f"(d[1]), "=f"(d[2]), "=f"(d[3])
        : "r"(a[0]), "r"(a[1]), "r"(a[2]), "r"(a[3]), "r"(b[0]), "r"(b[1]),
          "f"(0.0f), "f"(0.0f), "f"(0.0f), "f"(0.0f));
}

// ------------------------- split fp32 -> 2x fp16 ---------------------------
__device__ __forceinline__ void split2(float v, __half& h0, __half& h1) {
    h0 = __float2half_rn(v);
    float r = v - __half2float(h0);
    h1 = __float2half_rn(r);
}

__global__ __launch_bounds__(256) void split_x_kernel(const float* __restrict__ src)
{
    int i = blockIdx.x * blockDim.x + threadIdx.x;   // one float4 per thread
    float4 a = reinterpret_cast<const float4*>(src)[i];
    float v[4] = {a.x, a.y, a.z, a.w};
    __half h0[4], h1[4];
#pragma unroll
    for (int j = 0; j < 4; j++) split2(v[j], h0[j], h1[j]);
    __half2 p;
    p = {h0[0], h0[1]}; reinterpret_cast<__half2*>(g_A0h)[2*i  ] = p;
    p = {h0[2], h0[3]}; reinterpret_cast<__half2*>(g_A0h)[2*i+1] = p;
    p = {h1[0], h1[1]}; reinterpret_cast<__half2*>(g_A1h)[2*i  ] = p;
    p = {h1[2], h1[3]}; reinterpret_cast<__half2*>(g_A1h)[2*i+1] = p;
}

__global__ __launch_bounds__(256) void split_w_kernel(const float* __restrict__ src)
{
    int i = blockIdx.x * blockDim.x + threadIdx.x;
    float4 a = reinterpret_cast<const float4*>(src)[i];
    float v[4] = {a.x * WSCALE, a.y * WSCALE, a.z * WSCALE, a.w * WSCALE};
    __half h0[4], h1[4];
#pragma unroll
    for (int j = 0; j < 4; j++) split2(v[j], h0[j], h1[j]);
    __half2 p;
    p = {h0[0], h0[1]}; reinterpret_cast<__half2*>(g_B0h)[2*i  ] = p;
    p = {h0[2], h0[3]}; reinterpret_cast<__half2*>(g_B0h)[2*i+1] = p;
    p = {h1[0], h1[1]}; reinterpret_cast<__half2*>(g_B1h)[2*i  ] = p;
    p = {h1[2], h1[3]}; reinterpret_cast<__half2*>(g_B1h)[2*i+1] = p;
}

// ------------------------------ GEMM kernel --------------------------------
// BM=64, BN=128, BK=128. 256 threads = 8 warps (2 wm x 4 wn), warp tile 32x32.
// Tiles k-chunked: A split = [2 kc][64 rows][128B] = 16KB (x2 splits = 32KB),
// B split = [2 kc][128 rows][128B] = 32KB (x2 = 64KB). 96KB single-buffered
// -> 2 CTAs/SM. Per stage: 8 k16 steps, 192 mma/warp.
constexpr int BM = 64, BN = 128, BK = 128;
constexpr int NST = IN_DIM / BK;              // 16 stages
constexpr int ACH = 64 * 128;                 // 8 KB per A kchunk
constexpr int BCH = 128 * 128;                // 16 KB per B kchunk
constexpr int ATILE = 2 * ACH;                // 16 KB
constexpr int BTILE = 2 * BCH;                // 32 KB
constexpr int G_SMEM = 2 * ATILE + 2 * BTILE; // 98304

__global__ __launch_bounds__(256, 2)
void gemm3_kernel(const float* __restrict__ bias)
{
    extern __shared__ char smem[];
    const uint32_t sb = smem_u32(smem);
    const int tid  = threadIdx.x;
    const int wid  = tid >> 5;
    const int lane = tid & 31;
    const int bm = blockIdx.y * BM;
    const int bn = blockIdx.x * BN;
    const int warp_m = wid & 1;      // 0..1 (32 rows)
    const int warp_n = wid >> 1;     // 0..3 (32 cols)
    const int mi = lane >> 3, r8 = lane & 7;

    const __half* A0 = g_A0h + (size_t)bm * IN_DIM;
    const __half* A1 = g_A1h + (size_t)bm * IN_DIM;
    const __half* B0 = g_B0h + (size_t)bn * IN_DIM;
    const __half* B1 = g_B1h + (size_t)bn * IN_DIM;

    const uint32_t sA0 = sb;
    const uint32_t sA1 = sb + ATILE;
    const uint32_t sB0 = sb + 2 * ATILE;
    const uint32_t sB1 = sb + 2 * ATILE + BTILE;

    auto stage_load = [&](int s) {
        const int k0 = s * BK;
        // A tiles: 1024 chunks each (4 per thread)
#pragma unroll
        for (int t = 0; t < 2; t++) {
            const __half* base = (t == 0) ? A0 : A1;
            uint32_t stile = (t == 0) ? sA0 : sA1;
#pragma unroll
            for (int u = 0; u < 4; u++) {
                int v = tid + 256 * u;          // 0..1023
                int kc = v >> 9;                // 0..1
                int r  = (v >> 3) & 63;
                int cb = (v & 7) * 16;
                const char* g = (const char*)(base + (size_t)r * IN_DIM + k0 + kc * 64) + cb;
                asm volatile("cp.async.cg.shared.global [%0], [%1], 16;"
                             :: "r"(stile + kc * ACH + SW128(r * 128 + cb)), "l"(g));
            }
        }
        // B tiles: 2048 chunks each (8 per thread)
#pragma unroll
        for (int t = 0; t < 2; t++) {
            const __half* base = (t == 0) ? B0 : B1;
            uint32_t stile = (t == 0) ? sB0 : sB1;
#pragma unroll
            for (int u = 0; u < 8; u++) {
                int v = tid + 256 * u;          // 0..2047
                int kc = v >> 10;               // 0..1
                int r  = (v >> 3) & 127;
                int cb = (v & 7) * 16;
                const char* g = (const char*)(base + (size_t)r * IN_DIM + k0 + kc * 64) + cb;
                asm volatile("cp.async.cg.shared.global [%0], [%1], 16;"
                             :: "r"(stile + kc * BCH + SW128(r * 128 + cb)), "l"(g));
            }
        }
        asm volatile("cp.async.commit_group;" ::: "memory");
    };

    float hi[2][4][4];
#pragma unroll
    for (int mt = 0; mt < 2; mt++)
#pragma unroll
        for (int nf = 0; nf < 4; nf++)
#pragma unroll
            for (int j = 0; j < 4; j++) hi[mt][nf][j] = 0.0f;

    stage_load(0);

    for (int s = 0; s < NST; s++) {
        asm volatile("cp.async.wait_group 0;" ::: "memory");
        __syncthreads();

        float tmp[2][4][4];

        // ---- main path a0*b0: 2 chain-4 groups, RN drain into hi ----
#pragma unroll
        for (int grp = 0; grp < 2; grp++) {
#pragma unroll
            for (int q = 0; q < 4; q++) {
                const int ks = grp * 4 + q;
                const uint32_t akc = (uint32_t)(ks >> 2) * ACH;
                const uint32_t bkc = (uint32_t)(ks >> 2) * BCH;
                const int ik = (ks & 3) * 32;
                const int kb_a = ik + (mi >> 1) * 16;
                const int kb_b = ik + (mi & 1) * 16;
                uint32_t af[2][4], bfr[2][4];
#pragma unroll
                for (int mt = 0; mt < 2; mt++) {
                    int row = warp_m * 32 + mt * 16 + (mi & 1) * 8 + r8;
                    ldmx4(af[mt], sA0 + akc + SW128(row * 128 + kb_a));
                }
#pragma unroll
                for (int np = 0; np < 2; np++) {
                    int n = warp_n * 32 + np * 16 + (mi >> 1) * 8 + r8;
                    ldmx4(bfr[np], sB0 + bkc + SW128(n * 128 + kb_b));
                }
                if (q == 0) {
#pragma unroll
                    for (int mt = 0; mt < 2; mt++)
#pragma unroll
                        for (int nf = 0; nf < 4; nf++)
                            mma16816_z(tmp[mt][nf], af[mt], &bfr[nf >> 1][(nf & 1) * 2]);
                } else {
#pragma unroll
                    for (int mt = 0; mt < 2; mt++)
#pragma unroll
                        for (int nf = 0; nf < 4; nf++)
                            mma16816(tmp[mt][nf], af[mt], &bfr[nf >> 1][(nf & 1) * 2]);
                }
            }
#pragma unroll
            for (int mt = 0; mt < 2; mt++)
#pragma unroll
                for (int nf = 0; nf < 4; nf++)
#pragma unroll
                    for (int j = 0; j < 4; j++)
                        hi[mt][nf][j] = __fadd_rn(hi[mt][nf][j], tmp[mt][nf][j]);
        }

        // ---- smalls a0*b1 + a1*b0: TC-chained over the stage, drain ----
#pragma unroll
        for (int ks = 0; ks < 8; ks++) {
            const uint32_t akc = (uint32_t)(ks >> 2) * ACH;
            const uint32_t bkc = (uint32_t)(ks >> 2) * BCH;
            const int ik = (ks & 3) * 32;
            const int kb_a = ik + (mi >> 1) * 16;
            const int kb_b = ik + (mi & 1) * 16;
            uint32_t af0[2][4], af1[2][4], bfr[2][4];
#pragma unroll
            for (int mt = 0; mt < 2; mt++) {
                int row = warp_m * 32 + mt * 16 + (mi & 1) * 8 + r8;
                ldmx4(af0[mt], sA0 + akc + SW128(row * 128 + kb_a));
                ldmx4(af1[mt], sA1 + akc + SW128(row * 128 + kb_a));
            }
            // a0 * b1
#pragma unroll
            for (int np = 0; np < 2; np++) {
                int n = warp_n * 32 + np * 16 + (mi >> 1) * 8 + r8;
                ldmx4(bfr[np], sB1 + bkc + SW128(n * 128 + kb_b));
            }
            if (ks == 0) {
#pragma unroll
                for (int mt = 0; mt < 2; mt++)
#pragma unroll
                    for (int nf = 0; nf < 4; nf++)
                        mma16816_z(tmp[mt][nf], af0[mt], &bfr[nf >> 1][(nf & 1) * 2]);
            } else {
#pragma unroll
                for (int mt = 0; mt < 2; mt++)
#pragma unroll
                    for (int nf = 0; nf < 4; nf++)
                        mma16816(tmp[mt][nf], af0[mt], &bfr[nf >> 1][(nf & 1) * 2]);
            }
            // a1 * b0
#pragma unroll
            for (int np = 0; np < 2; np++) {
                int n = warp_n * 32 + np * 16 + (mi >> 1) * 8 + r8;
                ldmx4(bfr[np], sB0 + bkc + SW128(n * 128 + kb_b));
            }
#pragma unroll
            for (int mt = 0; mt < 2; mt++)
#pragma unroll
                for (int nf = 0; nf < 4; nf++)
                    mma16816(tmp[mt][nf], af1[mt], &bfr[nf >> 1][(nf & 1) * 2]);
        }
#pragma unroll
        for (int mt = 0; mt < 2; mt++)
#pragma unroll
            for (int nf = 0; nf < 4; nf++)
#pragma unroll
                for (int j = 0; j < 4; j++)
                    hi[mt][nf][j] = __fadd_rn(hi[mt][nf][j], tmp[mt][nf][j]);

        __syncthreads();                        // WAR before reload
        if (s + 1 < NST) stage_load(s + 1);
    }

    // Epilogue: hi/4096 + bias -> g_cur
    const int qr = lane >> 2;
    const int qc = (lane & 3) * 2;
#pragma unroll
    for (int mt = 0; mt < 2; mt++)
#pragma unroll
        for (int h = 0; h < 2; h++) {
            int row = bm + warp_m * 32 + mt * 16 + h * 8 + qr;
            float* dst = g_cur + (size_t)row * OUT_DIM + bn + warp_n * 32 + qc;
            const float* bp = bias + bn + warp_n * 32 + qc;
#pragma unroll
            for (int nf = 0; nf < 4; nf++) {
                float2 v;
                v.x = __fadd_rn(__fmul_rn(hi[mt][nf][h*2+0], INVWS), bp[nf*8+0]);
                v.y = __fadd_rn(__fmul_rn(hi[mt][nf][h*2+1], INVWS), bp[nf*8+1]);
                *reinterpret_cast<float2*>(dst + nf * 8) = v;
            }
        }
}

// ------------------------------ LIF scan -----------------------------------
__global__ __launch_bounds__(256) void lif_scan_kernel(float* __restrict__ out)
{
    const int idx = blockIdx.x * blockDim.x + threadIdx.x;
    const int BO  = B_DIM * OUT_DIM;
    float mem = 0.0f;
#pragma unroll
    for (int t = 0; t < T_DIM; t++) {
        float c = g_cur[(size_t)t * BO + idx];
        mem = __fadd_rn(__fmul_rn(mem, DECAY_V), c);
        float spk = (__fadd_rn(mem, -THR_V) > 0.0f) ? 1.0f : 0.0f;
        mem = __fadd_rn(mem, -spk * THR_V);
        out[(size_t)t * BO + idx] = spk;
    }
}

// ---------------------------------------------------------------------------
extern "C" void kernel_launch(void* const* d_in, const int* in_sizes, int n_in,
                              void* d_out, int out_size)
{
    const float* x = (const float*)d_in[0];
    const float* W = (const float*)d_in[1];
    const float* b = (const float*)d_in[2];
    float* out = (float*)d_out;

    split_x_kernel<<<(M_DIM * (size_t)IN_DIM / 4) / 256, 256>>>(x);
    split_w_kernel<<<(OUT_DIM * (size_t)IN_DIM / 4) / 256, 256>>>(W);

    cudaFuncSetAttribute(gemm3_kernel,
                         cudaFuncAttributeMaxDynamicSharedMemorySize, G_SMEM);
    dim3 grid(OUT_DIM / BN, M_DIM / BM);      // (16, 128)
    gemm3_kernel<<<grid, 256, G_SMEM>>>(b);

    lif_scan_kernel<<<(B_DIM * OUT_DIM) / 256, 256>>>(out);
}